// round 8
// baseline (speedup 1.0000x reference)
#include <cuda_runtime.h>
#include <cstdint>

#define B_SZ    16
#define IN_F    8192
#define OUT_F   8192
#define GRP     128
#define NGRP    64
#define CHUNK   512            // x columns per chunk
#define NCHUNK  16
#define THREADS 512
#define RPB     64             // rows per block
#define WST     4              // W ring stages
#define XST     2              // x ring stages
#define XPAD    20             // floats per staged column (80B stride, conflict-free)

#define WS_STAGE_F  (RPB * GRP)        // 8192 floats / W stage
#define XR_STAGE_F  (CHUNK * XPAD)     // 10240 floats / x stage
#define WS_OFF      128
#define XR_OFF      (WS_OFF + WST * WS_STAGE_F * 4)   // 131200
#define SC_OFF      (XR_OFF + XST * XR_STAGE_F * 4)   // 213120
#define SMEM_TOTAL  (SC_OFF + RPB * NGRP * 4)         // 229504

typedef unsigned long long ull;

__device__ __forceinline__ ull pack2(float v) {
    ull r; asm("mov.b64 %0, {%1, %1};" : "=l"(r) : "f"(v)); return r;
}
__device__ __forceinline__ void fma2(ull& d, ull a, ull b) {
    asm("fma.rn.f32x2 %0, %1, %2, %0;" : "+l"(d) : "l"(a), "l"(b));
}
__device__ __forceinline__ ull add2(ull a, ull b) {
    ull r; asm("add.rn.f32x2 %0, %1, %2;" : "=l"(r) : "l"(a), "l"(b)); return r;
}
__device__ __forceinline__ void unpack2(ull v, float& lo, float& hi) {
    asm("mov.b64 {%0, %1}, %2;" : "=f"(lo), "=f"(hi) : "l"(v));
}
__device__ __forceinline__ void cp_async16(uint32_t dst, const float* src) {
    asm volatile("cp.async.cg.shared.global [%0], [%1], 16;" :: "r"(dst), "l"(src));
}
__device__ __forceinline__ void mbar_init(uint32_t a, uint32_t cnt) {
    asm volatile("mbarrier.init.shared.b64 [%0], %1;" :: "r"(a), "r"(cnt) : "memory");
}
__device__ __forceinline__ void mbar_arrive(uint32_t a) {
    asm volatile("mbarrier.arrive.release.cta.shared::cta.b64 _, [%0];" :: "r"(a) : "memory");
}
__device__ __forceinline__ void cpasync_mbar_arrive_noinc(uint32_t a) {
    asm volatile("cp.async.mbarrier.arrive.noinc.shared::cta.b64 [%0];" :: "r"(a) : "memory");
}
__device__ __forceinline__ void mbar_wait(uint32_t a, uint32_t parity) {
    asm volatile(
        "{\n\t.reg .pred P;\n\t"
        "WL_%=:\n\t"
        "mbarrier.try_wait.parity.acquire.cta.shared::cta.b64 P, [%0], %1, 0x989680;\n\t"
        "@P bra.uni WD_%=;\n\t"
        "bra.uni WL_%=;\n\t"
        "WD_%=:\n\t}"
        :: "r"(a), "r"(parity) : "memory");
}

__global__ void __launch_bounds__(THREADS, 1)
axcore_linear_kernel(const float* __restrict__ x,
                     const float* __restrict__ W,
                     const float* __restrict__ scale,
                     const float* __restrict__ bias,
                     float* __restrict__ out)
{
    extern __shared__ char smem[];
    float* ws = reinterpret_cast<float*>(smem + WS_OFF);
    float* xr = reinterpret_cast<float*>(smem + XR_OFF);
    float* sc = reinterpret_cast<float*>(smem + SC_OFF);
    const uint32_t smem_u32 = (uint32_t)__cvta_generic_to_shared(smem);
#define FULLW(s)  (smem_u32 + (s) * 8)
#define EMPTYW(s) (smem_u32 + 32 + (s) * 8)
#define FULLX(s)  (smem_u32 + 64 + (s) * 8)

    const int tid  = threadIdx.x;
    const int lane = tid & 31;
    const int warp = tid >> 5;
    const int half = warp >> 3;          // batch half
    const int wr0  = (warp & 7) * 8;     // warp's first row in block
    const int row0 = blockIdx.x * RPB;
    const float* Wb = W + (size_t)row0 * IN_F;
    const bool prod = (warp < 4);        // producer warps (tid < 128)

    if (tid == 0) {
#pragma unroll
        for (int s = 0; s < WST; s++) {
            mbar_init(FULLW(s), 128);    // noinc cp.async arrivals (128 prod threads)
            mbar_init(EMPTYW(s), 16);    // elected per-warp arrives
        }
#pragma unroll
        for (int s = 0; s < XST; s++) mbar_init(FULLX(s), 128);
    }
    __syncthreads();

    // ---- W group gi -> ring slot (producers only): 16x cp.async16 per thread
#define ISSUE_W(gi, slot) do {                                                \
        const float* _src = Wb + (size_t)(gi) * GRP;                          \
        const uint32_t _db = smem_u32 + WS_OFF + (slot) * (WS_STAGE_F * 4);   \
        _Pragma("unroll")                                                     \
        for (int j = 0; j < 16; j++) {                                        \
            const int i = tid + 128 * j;        /* 0..2047 */                 \
            const int r = i >> 5, cf = i & 31;  /* 64 rows x 32 x 16B */      \
            cp_async16(_db + (uint32_t)(r * GRP + cf * 4) * 4,                \
                       _src + (size_t)r * IN_F + cf * 4);                     \
        }                                                                     \
        cpasync_mbar_arrive_noinc(FULLW(slot));                               \
    } while (0)

    // ---- x chunk -> transposed stage [col][XPAD] (producers, LDG+STS)
    //      thread: batch=tid>>3, cols (tid&7)+8i; STS banks all-distinct.
#define ISSUE_X(c, slot) do {                                                 \
        const int _b = tid >> 3, _c0 = tid & 7;                               \
        const float* _src = x + (size_t)_b * IN_F + (c) * CHUNK + _c0;        \
        float* _dst = xr + (slot) * XR_STAGE_F + _b;                          \
        _Pragma("unroll")                                                     \
        for (int wv = 0; wv < 8; wv++) {                                      \
            float _t[8];                                                      \
            _Pragma("unroll")                                                 \
            for (int j = 0; j < 8; j++) _t[j] = __ldg(_src + (wv*8 + j) * 8); \
            _Pragma("unroll")                                                 \
            for (int j = 0; j < 8; j++)                                       \
                _dst[(_c0 + (wv*8 + j) * 8) * XPAD] = _t[j];                  \
        }                                                                     \
        mbar_arrive(FULLX(slot));  /* release: orders STS before consumer */  \
    } while (0)

    // ---- prologue: 3 W stages ahead, x chunk 0; stage scales
    if (prod) { ISSUE_W(0, 0); ISSUE_W(1, 1); ISSUE_W(2, 2); ISSUE_X(0, 0); }
    for (int idx = tid; idx < RPB * NGRP; idx += THREADS)
        sc[idx] = scale[(size_t)row0 * NGRP + idx];
    __syncthreads();   // sc visible

    ull acc[8][4];
#pragma unroll
    for (int r = 0; r < 8; r++)
#pragma unroll
        for (int q = 0; q < 4; q++) acc[r][q] = 0ull;

    int cwsl = 0, cwph = 0;       // consumer W cursor
    int pwsl = WST - 1, pwph = 0; // producer W cursor (issues g+3)
    int cxsl = 0, cxph = 0;       // consumer X cursor (chunk g>>2)

    for (int g = 0; g < NGRP; g++) {
        if (prod) {
            if (g + 3 < NGRP) {
                mbar_wait(EMPTYW(pwsl), pwph ^ 1);
                ISSUE_W(g + 3, pwsl);
                // after this wait: all warps finished group g-1  =>
                // chunk (g>>2)-1 fully consumed => x slot (c+1)&1 reusable
                if ((g & 3) == 0) {
                    const int c = (g >> 2) + 1;
                    if (c < NCHUNK) ISSUE_X(c, c & 1);
                }
                if (++pwsl == WST) { pwsl = 0; pwph ^= 1; }
            }
        }
        mbar_wait(FULLW(cwsl), cwph);
        if ((g & 3) == 0) mbar_wait(FULLX(cxsl), cxph);

        const float* wst = ws + cwsl * WS_STAGE_F + wr0 * GRP;
        const int jb = (g & 3) * GRP;     // group offset within x chunk
        const float* xk = xr + cxsl * XR_STAGE_F + (jb + lane) * XPAD + half * 8;
        float s[8];
#pragma unroll
        for (int r = 0; r < 8; r++) s[r] = sc[(wr0 + r) * NGRP + g];

#pragma unroll
        for (int k = 0; k < 4; k++) {
            const int kc = lane + 32 * k;           // W col in group
            const ulonglong2* px =
                reinterpret_cast<const ulonglong2*>(xk + k * (32 * XPAD));
            ulonglong2 va = px[0], vb = px[1];      // batches 8h..8h+7 paired
            ull x2[4] = { va.x, va.y, vb.x, vb.y };
#pragma unroll
            for (int r = 0; r < 8; r++) {
                const ull w2 = pack2(wst[r * GRP + kc] * s[r]);
#pragma unroll
                for (int q = 0; q < 4; q++) fma2(acc[r][q], w2, x2[q]);
            }
        }

        if (lane == 0) mbar_arrive(EMPTYW(cwsl));
        if (++cwsl == WST) { cwsl = 0; cwph ^= 1; }
        if ((g & 3) == 3) { if (++cxsl == XST) { cxsl = 0; cxph ^= 1; } }
    }

    // ---- butterfly reduction across lanes
#pragma unroll
    for (int r = 0; r < 8; r++)
#pragma unroll
        for (int q = 0; q < 4; q++) {
            ull v = acc[r][q];
#pragma unroll
            for (int off = 16; off > 0; off >>= 1)
                v = add2(v, __shfl_xor_sync(0xffffffffu, v, off));
            acc[r][q] = v;
        }

    // ---- writeback: lane (r*4+q) -> row wr0+r, batches (half*8+2q, +1)
#pragma unroll
    for (int r = 0; r < 8; r++)
#pragma unroll
        for (int q = 0; q < 4; q++)
            if (lane == r * 4 + q) {
                const int row = row0 + wr0 + r;
                const int b0  = half * 8 + 2 * q;
                const float bv = __ldg(bias + row);
                float lo, hi;
                unpack2(acc[r][q], lo, hi);
                out[(size_t)b0 * OUT_F + row]       = lo + bv;
                out[(size_t)(b0 + 1) * OUT_F + row] = hi + bv;
            }
}

extern "C" void kernel_launch(void* const* d_in, const int* in_sizes, int n_in,
                              void* d_out, int out_size)
{
    const float* x     = (const float*)d_in[0]; // [16, 8192]
    const float* W     = (const float*)d_in[1]; // [8192, 8192]
    const float* scale = (const float*)d_in[2]; // [8192, 64]
    const float* bias  = (const float*)d_in[3]; // [1, 8192]
    // d_in[4] = types — constant lookup in reference; no float math: unused
    float* out = (float*)d_out;                 // [16, 8192]

    cudaFuncSetAttribute(axcore_linear_kernel,
                         cudaFuncAttributeMaxDynamicSharedMemorySize, SMEM_TOTAL);

    dim3 grid(OUT_F / RPB); // 128
    dim3 block(THREADS);    // 512
    axcore_linear_kernel<<<grid, block, SMEM_TOTAL>>>(x, W, scale, bias, out);
}

// round 9
// speedup vs baseline: 1.2032x; 1.2032x over previous
#include <cuda_runtime.h>
#include <cstdint>

#define B_SZ    16
#define IN_F    8192
#define OUT_F   8192
#define GRP     128
#define NGRP    64
#define CHUNK   512            // x columns per chunk
#define NCHUNK  16
#define THREADS 512
#define RPB     64             // rows per block
#define WST     4              // W ring stages
#define XST     2              // x ring stages
#define XPAD    20             // floats per staged column (80B stride, conflict-free)

#define WS_STAGE_F  (RPB * GRP)        // 8192 floats / W stage
#define XR_STAGE_F  (CHUNK * XPAD)     // 10240 floats / x stage
#define WS_OFF      128
#define XR_OFF      (WS_OFF + WST * WS_STAGE_F * 4)   // 131200
#define SC_OFF      (XR_OFF + XST * XR_STAGE_F * 4)   // 213120
#define SMEM_TOTAL  (SC_OFF + RPB * NGRP * 4)         // 229504

typedef unsigned long long ull;

// pre-transposed x: [IN_F][B_SZ]  (512 KB static scratch)
__device__ float g_xT[IN_F * B_SZ];

__device__ __forceinline__ ull pack2(float v) {
    ull r; asm("mov.b64 %0, {%1, %1};" : "=l"(r) : "f"(v)); return r;
}
__device__ __forceinline__ void fma2(ull& d, ull a, ull b) {
    asm("fma.rn.f32x2 %0, %1, %2, %0;" : "+l"(d) : "l"(a), "l"(b));
}
__device__ __forceinline__ ull add2(ull a, ull b) {
    ull r; asm("add.rn.f32x2 %0, %1, %2;" : "=l"(r) : "l"(a), "l"(b)); return r;
}
__device__ __forceinline__ void unpack2(ull v, float& lo, float& hi) {
    asm("mov.b64 {%0, %1}, %2;" : "=f"(lo), "=f"(hi) : "l"(v));
}
__device__ __forceinline__ void cp_async16(uint32_t dst, const float* src) {
    asm volatile("cp.async.cg.shared.global [%0], [%1], 16;" :: "r"(dst), "l"(src));
}
__device__ __forceinline__ void mbar_init(uint32_t a, uint32_t cnt) {
    asm volatile("mbarrier.init.shared.b64 [%0], %1;" :: "r"(a), "r"(cnt) : "memory");
}
__device__ __forceinline__ void mbar_arrive(uint32_t a) {
    asm volatile("mbarrier.arrive.release.cta.shared::cta.b64 _, [%0];" :: "r"(a) : "memory");
}
__device__ __forceinline__ void cpasync_mbar_arrive_noinc(uint32_t a) {
    asm volatile("cp.async.mbarrier.arrive.noinc.shared::cta.b64 [%0];" :: "r"(a) : "memory");
}
__device__ __forceinline__ void mbar_wait(uint32_t a, uint32_t parity) {
    asm volatile(
        "{\n\t.reg .pred P;\n\t"
        "WL_%=:\n\t"
        "mbarrier.try_wait.parity.acquire.cta.shared::cta.b64 P, [%0], %1, 0x989680;\n\t"
        "@P bra.uni WD_%=;\n\t"
        "bra.uni WL_%=;\n\t"
        "WD_%=:\n\t}"
        :: "r"(a), "r"(parity) : "memory");
}

// ---- pre-pass: x [16][8192] -> g_xT [8192][16]
__global__ void __launch_bounds__(256, 1)
transpose_x_kernel(const float* __restrict__ x)
{
    const int col = blockIdx.x * 256 + threadIdx.x;
    float v[B_SZ];
#pragma unroll
    for (int b = 0; b < B_SZ; b++) v[b] = __ldg(x + (size_t)b * IN_F + col);
    float4* dst = reinterpret_cast<float4*>(g_xT + (size_t)col * B_SZ);
#pragma unroll
    for (int q = 0; q < 4; q++)
        dst[q] = make_float4(v[4*q], v[4*q+1], v[4*q+2], v[4*q+3]);
}

__global__ void __launch_bounds__(THREADS, 1)
axcore_linear_kernel(const float* __restrict__ W,
                     const float* __restrict__ scale,
                     const float* __restrict__ bias,
                     float* __restrict__ out)
{
    extern __shared__ char smem[];
    float* ws = reinterpret_cast<float*>(smem + WS_OFF);
    float* xr = reinterpret_cast<float*>(smem + XR_OFF);
    float* sc = reinterpret_cast<float*>(smem + SC_OFF);
    const uint32_t smem_u32 = (uint32_t)__cvta_generic_to_shared(smem);
#define FULLW(s)  (smem_u32 + (s) * 8)
#define EMPTYW(s) (smem_u32 + 32 + (s) * 8)
#define FULLX(s)  (smem_u32 + 64 + (s) * 8)

    const int tid  = threadIdx.x;
    const int lane = tid & 31;
    const int warp = tid >> 5;
    const int half = warp >> 3;          // batch half
    const int wr0  = (warp & 7) * 8;     // warp's first row in block
    const int row0 = blockIdx.x * RPB;
    const float* Wb = W + (size_t)row0 * IN_F;
    const bool prod = (warp < 4);        // producer warps (tid < 128)

    if (tid == 0) {
#pragma unroll
        for (int s = 0; s < WST; s++) {
            mbar_init(FULLW(s), 128);    // noinc cp.async arrivals
            mbar_init(EMPTYW(s), 16);    // elected per-warp arrives
        }
#pragma unroll
        for (int s = 0; s < XST; s++) mbar_init(FULLX(s), 128);
    }
    __syncthreads();

    // ---- W group gi -> ring slot (producers, 16x cp.async16 each)
#define ISSUE_W(gi, slot) do {                                                \
        const float* _src = Wb + (size_t)(gi) * GRP;                          \
        const uint32_t _db = smem_u32 + WS_OFF + (slot) * (WS_STAGE_F * 4);   \
        _Pragma("unroll")                                                     \
        for (int j = 0; j < 16; j++) {                                        \
            const int i = tid + 128 * j;        /* 0..2047 */                 \
            const int r = i >> 5, cf = i & 31;  /* 64 rows x 32 x 16B */      \
            cp_async16(_db + (uint32_t)(r * GRP + cf * 4) * 4,                \
                       _src + (size_t)r * IN_F + cf * 4);                     \
        }                                                                     \
        cpasync_mbar_arrive_noinc(FULLW(slot));                               \
    } while (0)

    // ---- x chunk -> [col][XPAD] stage via cp.async from g_xT (fully async)
#define ISSUE_X(c, slot) do {                                                 \
        const float* _src = g_xT + (size_t)(c) * CHUNK * B_SZ;                \
        const uint32_t _db = smem_u32 + XR_OFF + (slot) * (XR_STAGE_F * 4);   \
        _Pragma("unroll")                                                     \
        for (int j = 0; j < 16; j++) {                                        \
            const int i = tid + 128 * j;          /* 0..2047 */               \
            const int cl = i >> 2, q = i & 3;     /* 512 cols x 4 x 16B */    \
            cp_async16(_db + (uint32_t)(cl * XPAD + q * 4) * 4,               \
                       _src + cl * B_SZ + q * 4);                             \
        }                                                                     \
        cpasync_mbar_arrive_noinc(FULLX(slot));                               \
    } while (0)

    // ---- prologue: 3 W stages ahead + x chunk 0; stage scales
    if (prod) { ISSUE_W(0, 0); ISSUE_W(1, 1); ISSUE_W(2, 2); ISSUE_X(0, 0); }
    for (int idx = tid; idx < RPB * NGRP; idx += THREADS)
        sc[idx] = scale[(size_t)row0 * NGRP + idx];
    __syncthreads();   // sc visible

    ull acc[8][4];
#pragma unroll
    for (int r = 0; r < 8; r++)
#pragma unroll
        for (int q = 0; q < 4; q++) acc[r][q] = 0ull;

    int cwsl = 0, cwph = 0;       // consumer W cursor
    int pwsl = WST - 1, pwph = 0; // producer W cursor (issues g+3)
    int cxsl = 0, cxph = 0;       // consumer X cursor (chunk g>>2)

    for (int g = 0; g < NGRP; g++) {
        if (prod && g + 3 < NGRP) {
            mbar_wait(EMPTYW(pwsl), pwph ^ 1);
            ISSUE_W(g + 3, pwsl);
            // EMPTYW pass => all warps finished group g-1 => chunk (g>>2)-1
            // fully consumed => x slot (c+1)&1 reusable.
            if ((g & 3) == 0) {
                const int c = (g >> 2) + 1;
                if (c < NCHUNK) ISSUE_X(c, c & 1);
            }
            if (++pwsl == WST) { pwsl = 0; pwph ^= 1; }
        }
        mbar_wait(FULLW(cwsl), cwph);
        if ((g & 3) == 0) mbar_wait(FULLX(cxsl), cxph);

        const float* wst = ws + cwsl * WS_STAGE_F + wr0 * GRP;
        const int jb = (g & 3) * GRP;     // group offset within x chunk
        const float* xbase = xr + cxsl * XR_STAGE_F + jb * XPAD + half * 8;
        float s[8];
#pragma unroll
        for (int r = 0; r < 8; r++) s[r] = sc[(wr0 + r) * NGRP + g];

#pragma unroll
        for (int k = 0; k < 4; k++) {
            const int kk = (k + (half << 1)) & 3;   // de-phase halves
            const int kc = lane + 32 * kk;          // W col in group
            const float* xp = xbase + kc * XPAD;
            ulonglong2 va = *reinterpret_cast<const ulonglong2*>(xp);
            ulonglong2 vb = *reinterpret_cast<const ulonglong2*>(xp + 4);
            ull x2[4] = { va.x, va.y, vb.x, vb.y };  // batch pairs of this half
#pragma unroll
            for (int r = 0; r < 8; r++) {
                const ull w2 = pack2(wst[r * GRP + kc] * s[r]);
#pragma unroll
                for (int q = 0; q < 4; q++) fma2(acc[r][q], w2, x2[q]);
            }
        }

        if (lane == 0) mbar_arrive(EMPTYW(cwsl));
        if (++cwsl == WST) { cwsl = 0; cwph ^= 1; }
        if ((g & 3) == 3) { if (++cxsl == XST) { cxsl = 0; cxph ^= 1; } }
    }

    // ---- butterfly reduction across lanes
#pragma unroll
    for (int r = 0; r < 8; r++)
#pragma unroll
        for (int q = 0; q < 4; q++) {
            ull v = acc[r][q];
#pragma unroll
            for (int off = 16; off > 0; off >>= 1)
                v = add2(v, __shfl_xor_sync(0xffffffffu, v, off));
            acc[r][q] = v;
        }

    // ---- writeback: lane (r*4+q) -> row wr0+r, batches (half*8+2q, +1)
#pragma unroll
    for (int r = 0; r < 8; r++)
#pragma unroll
        for (int q = 0; q < 4; q++)
            if (lane == r * 4 + q) {
                const int row = row0 + wr0 + r;
                const int b0  = half * 8 + 2 * q;
                const float bv = __ldg(bias + row);
                float lo, hi;
                unpack2(acc[r][q], lo, hi);
                out[(size_t)b0 * OUT_F + row]       = lo + bv;
                out[(size_t)(b0 + 1) * OUT_F + row] = hi + bv;
            }
}

extern "C" void kernel_launch(void* const* d_in, const int* in_sizes, int n_in,
                              void* d_out, int out_size)
{
    const float* x     = (const float*)d_in[0]; // [16, 8192]
    const float* W     = (const float*)d_in[1]; // [8192, 8192]
    const float* scale = (const float*)d_in[2]; // [8192, 64]
    const float* bias  = (const float*)d_in[3]; // [1, 8192]
    // d_in[4] = types — constant lookup in reference; no float math: unused
    float* out = (float*)d_out;                 // [16, 8192]

    cudaFuncSetAttribute(axcore_linear_kernel,
                         cudaFuncAttributeMaxDynamicSharedMemorySize, SMEM_TOTAL);

    transpose_x_kernel<<<IN_F / 256, 256>>>(x);                 // x -> g_xT
    axcore_linear_kernel<<<OUT_F / RPB, THREADS, SMEM_TOTAL>>>(W, scale, bias, out);
}